// round 1
// baseline (speedup 1.0000x reference)
#include <cuda_runtime.h>

// Problem constants (fixed by the dataset)
#define BATCH   4
#define TSEQ    2048
#define DM      1024
#define HEADS   16
#define DK      64
#define BT      (BATCH * TSEQ)   // 8192 rows

// Scratch (static device globals; allocation-free per harness rules)
__device__ float g_qp[BT * DM];
__device__ float g_kp[BT * DM];
__device__ float g_vp[BT * DM];
__device__ float g_ctx[BT * DM];

// ---------------------------------------------------------------------------
// GEMM: C[M, DM] = A[M, K] @ W[DM, K]^T + bias[DM]
// 64x64 tile, 256 threads, 4x4 microtile, K-tile = 16.
// Both A and W are K-major along reduction -> coalesced global loads,
// staged transposed in smem so the inner loop uses float4 LDS.
// ---------------------------------------------------------------------------
__global__ void __launch_bounds__(256) gemm_nt_bias(
    const float* __restrict__ A, const float* __restrict__ W,
    const float* __restrict__ bias, float* __restrict__ C, int K)
{
    __shared__ float As[16][68];
    __shared__ float Ws[16][68];

    const int tid = threadIdx.x;
    const int tx = tid & 15;
    const int ty = tid >> 4;
    const int bm = blockIdx.y * 64;
    const int bn = blockIdx.x * 64;

    // staging indices: each thread loads one float4 of A and one of W per k-tile
    const int lr = tid >> 2;          // 0..63 : row within tile
    const int lc = (tid & 3) << 2;    // 0,4,8,12 : k offset

    const float* Ag = A + (size_t)(bm + lr) * K + lc;
    const float* Wg = W + (size_t)(bn + lr) * K + lc;

    float acc[4][4];
#pragma unroll
    for (int i = 0; i < 4; i++)
#pragma unroll
        for (int j = 0; j < 4; j++) acc[i][j] = 0.f;

    for (int k0 = 0; k0 < K; k0 += 16) {
        float4 av = *(const float4*)(Ag + k0);
        float4 wv = *(const float4*)(Wg + k0);
        As[lc + 0][lr] = av.x; As[lc + 1][lr] = av.y;
        As[lc + 2][lr] = av.z; As[lc + 3][lr] = av.w;
        Ws[lc + 0][lr] = wv.x; Ws[lc + 1][lr] = wv.y;
        Ws[lc + 2][lr] = wv.z; Ws[lc + 3][lr] = wv.w;
        __syncthreads();

#pragma unroll
        for (int k = 0; k < 16; k++) {
            float4 a = *(const float4*)&As[k][ty << 2];
            float4 b = *(const float4*)&Ws[k][tx << 2];
            acc[0][0] += a.x * b.x; acc[0][1] += a.x * b.y;
            acc[0][2] += a.x * b.z; acc[0][3] += a.x * b.w;
            acc[1][0] += a.y * b.x; acc[1][1] += a.y * b.y;
            acc[1][2] += a.y * b.z; acc[1][3] += a.y * b.w;
            acc[2][0] += a.z * b.x; acc[2][1] += a.z * b.y;
            acc[2][2] += a.z * b.z; acc[2][3] += a.z * b.w;
            acc[3][0] += a.w * b.x; acc[3][1] += a.w * b.y;
            acc[3][2] += a.w * b.z; acc[3][3] += a.w * b.w;
        }
        __syncthreads();
    }

    const int n = bn + (tx << 2);
    float4 bv = *(const float4*)&bias[n];
#pragma unroll
    for (int i = 0; i < 4; i++) {
        const int m = bm + (ty << 2) + i;
        float4 o;
        o.x = acc[i][0] + bv.x;
        o.y = acc[i][1] + bv.y;
        o.z = acc[i][2] + bv.z;
        o.w = acc[i][3] + bv.w;
        *(float4*)&C[(size_t)m * DM + n] = o;
    }
}

// ---------------------------------------------------------------------------
// Flash attention, fp32. One block = one (b,h) x 128 query rows.
// 256 threads: 2 threads per query row, each owning 32 of the 64 head dims.
// Key/value tiles of 32 rows staged in smem; online softmax; mask applied
// as additive -1e30 on key positions.
// ---------------------------------------------------------------------------
__global__ void __launch_bounds__(256) attn_kernel(
    const float* __restrict__ qp, const float* __restrict__ kp,
    const float* __restrict__ vp, const int* __restrict__ mask,
    float* __restrict__ ctx)
{
    __shared__ float Ks[32][72];
    __shared__ float Vs[32][72];
    __shared__ float mk[32];

    const int bh = blockIdx.y;
    const int b = bh >> 4;
    const int h = bh & 15;
    const int q0 = blockIdx.x * 128;
    const int tid = threadIdx.x;
    const int row = tid >> 1;     // 0..127
    const int half = tid & 1;     // which 32-dim half of d_k this thread owns

    // q row (strided head access: 32 contiguous floats)
    const float* qrow = qp + (size_t)(b * TSEQ + q0 + row) * DM + h * DK + half * 32;
    float q[32];
#pragma unroll
    for (int i = 0; i < 32; i++) q[i] = qrow[i];

    float acc[32];
#pragma unroll
    for (int i = 0; i < 32; i++) acc[i] = 0.f;
    float mrun = -1e30f;
    float lrun = 0.f;

    // staging indices: 256 threads load 32x64 floats (8 floats each) per array
    const int lr = tid >> 3;          // 0..31 key row
    const int lc = (tid & 7) << 3;    // 0,8,...,56

    const float* kbase = kp + (size_t)b * TSEQ * DM + h * DK;
    const float* vbase = vp + (size_t)b * TSEQ * DM + h * DK;
    const int*   mbase = mask + b * TSEQ;
    const float scale = 0.125f;       // 1/sqrt(64)

    for (int j0 = 0; j0 < TSEQ; j0 += 32) {
        const float* ksrc = kbase + (size_t)(j0 + lr) * DM + lc;
        const float* vsrc = vbase + (size_t)(j0 + lr) * DM + lc;
        float4 k1 = *(const float4*)(ksrc);
        float4 k2 = *(const float4*)(ksrc + 4);
        float4 v1 = *(const float4*)(vsrc);
        float4 v2 = *(const float4*)(vsrc + 4);
        *(float4*)&Ks[lr][lc]     = k1;
        *(float4*)&Ks[lr][lc + 4] = k2;
        *(float4*)&Vs[lr][lc]     = v1;
        *(float4*)&Vs[lr][lc + 4] = v2;
        if (tid < 32) mk[tid] = (mbase[j0 + tid] == 0) ? -1e30f : 0.f;
        __syncthreads();

        // scores for this tile (each thread: partial dot over its 32 dims,
        // combined with its pair lane via shfl)
        float s[32];
#pragma unroll
        for (int j = 0; j < 32; j++) {
            const float4* kr = (const float4*)&Ks[j][half * 32];
            float d = 0.f;
#pragma unroll
            for (int u = 0; u < 8; u++) {
                float4 kk = kr[u];
                d += q[4 * u + 0] * kk.x + q[4 * u + 1] * kk.y
                   + q[4 * u + 2] * kk.z + q[4 * u + 3] * kk.w;
            }
            d += __shfl_xor_sync(0xffffffffu, d, 1);
            s[j] = d * scale + mk[j];
        }

        // online softmax update
        float mt = mrun;
#pragma unroll
        for (int j = 0; j < 32; j++) mt = fmaxf(mt, s[j]);
        float corr = __expf(mrun - mt);
        mrun = mt;
        lrun *= corr;
#pragma unroll
        for (int i = 0; i < 32; i++) acc[i] *= corr;
#pragma unroll
        for (int j = 0; j < 32; j++) {
            float p = __expf(s[j] - mt);
            lrun += p;
            s[j] = p;
        }

        // accumulate P @ V for this thread's 32 dims
#pragma unroll
        for (int j = 0; j < 32; j++) {
            const float p = s[j];
            const float4* vr = (const float4*)&Vs[j][half * 32];
#pragma unroll
            for (int u = 0; u < 8; u++) {
                float4 vv = vr[u];
                acc[4 * u + 0] += p * vv.x;
                acc[4 * u + 1] += p * vv.y;
                acc[4 * u + 2] += p * vv.z;
                acc[4 * u + 3] += p * vv.w;
            }
        }
        __syncthreads();
    }

    const float inv = 1.f / lrun;
    float* dst = ctx + (size_t)(b * TSEQ + q0 + row) * DM + h * DK + half * 32;
#pragma unroll
    for (int i = 0; i < 32; i++) dst[i] = acc[i] * inv;
}

// ---------------------------------------------------------------------------
// Launch
// ---------------------------------------------------------------------------
extern "C" void kernel_launch(void* const* d_in, const int* in_sizes, int n_in,
                              void* d_out, int out_size)
{
    const float* Q    = (const float*)d_in[0];
    const float* Kin  = (const float*)d_in[1];
    const float* Vin  = (const float*)d_in[2];
    const int*   mask = (const int*)  d_in[3];
    const float* W_q  = (const float*)d_in[4];
    const float* b_q  = (const float*)d_in[5];
    const float* W_k  = (const float*)d_in[6];
    const float* b_k  = (const float*)d_in[7];
    const float* W_v  = (const float*)d_in[8];
    const float* b_v  = (const float*)d_in[9];
    const float* W_o  = (const float*)d_in[10];
    const float* b_o  = (const float*)d_in[11];
    float* out = (float*)d_out;

    float *qp, *kp, *vp, *ctx;
    cudaGetSymbolAddress((void**)&qp,  g_qp);
    cudaGetSymbolAddress((void**)&kp,  g_kp);
    cudaGetSymbolAddress((void**)&vp,  g_vp);
    cudaGetSymbolAddress((void**)&ctx, g_ctx);

    dim3 gg(DM / 64, BT / 64);   // (16, 128)
    gemm_nt_bias<<<gg, 256>>>(Q,   W_q, b_q, qp,  DM);
    gemm_nt_bias<<<gg, 256>>>(Kin, W_k, b_k, kp,  DM);
    gemm_nt_bias<<<gg, 256>>>(Vin, W_v, b_v, vp,  DM);

    attn_kernel<<<dim3(TSEQ / 128, BATCH * HEADS), 256>>>(qp, kp, vp, mask, ctx);

    gemm_nt_bias<<<gg, 256>>>(ctx, W_o, b_o, out, DM);
}

// round 2
// speedup vs baseline: 3.3031x; 3.3031x over previous
#include <cuda_runtime.h>
#include <cstdint>

#define BATCH   4
#define TSEQ    2048
#define DM      1024
#define HEADS   16
#define DK      64
#define BT      (BATCH * TSEQ)   // 8192 rows

// Scratch (static device globals; allocation-free per harness rules)
__device__ float g_qp[BT * DM];
__device__ float g_kp[BT * DM];
__device__ float g_vp[BT * DM];
__device__ float g_ctx[BT * DM];

// ---------------------------------------------------------------------------
// tf32 helpers
// ---------------------------------------------------------------------------
__device__ __forceinline__ uint32_t f2tf(float x) {
    uint32_t u;
    asm("cvt.rna.tf32.f32 %0, %1;" : "=r"(u) : "f"(x));
    return u;
}

__device__ __forceinline__ void mma_tf32(float c[4],
    uint32_t a0, uint32_t a1, uint32_t a2, uint32_t a3,
    uint32_t b0, uint32_t b1)
{
    asm volatile(
        "mma.sync.aligned.m16n8k8.row.col.f32.tf32.tf32.f32 "
        "{%0,%1,%2,%3}, {%4,%5,%6,%7}, {%8,%9}, {%0,%1,%2,%3};\n"
        : "+f"(c[0]), "+f"(c[1]), "+f"(c[2]), "+f"(c[3])
        : "r"(a0), "r"(a1), "r"(a2), "r"(a3), "r"(b0), "r"(b1));
}

// ---------------------------------------------------------------------------
// GEMM: C[M,1024] = A[M,1024] @ W[1024,1024]^T + bias, tf32 mma.
// Block tile 128x128, K-tile 32, 256 threads (8 warps = 2m x 4n),
// warp tile 64x32 = 4 m16-tiles x 4 n8-tiles.
// Smem [k][m] stride 133 -> conflict-free STS, <=2-way LDS on fragments.
// ---------------------------------------------------------------------------
__global__ void __launch_bounds__(256) gemm_tf32(
    const float* __restrict__ A, const float* __restrict__ W,
    const float* __restrict__ bias, float* __restrict__ C)
{
    __shared__ uint32_t As[32][133];
    __shared__ uint32_t Ws[32][133];

    const int tid  = threadIdx.x;
    const int lane = tid & 31;
    const int wid  = tid >> 5;
    const int wm   = (wid >> 2) * 64;   // 0 or 64
    const int wn   = (wid & 3) * 32;    // 0,32,64,96
    const int g    = lane >> 2;
    const int t    = lane & 3;
    const int bm   = blockIdx.y * 128;
    const int bn   = blockIdx.x * 128;

    const int lr = tid >> 3;            // 0..31
    const int lc = (tid & 7) << 2;      // 0,4,...,28

    const float* Ag = A + (size_t)(bm + lr) * DM + lc;
    const float* Wg = W + (size_t)(bn + lr) * DM + lc;

    float acc[4][4][4];
#pragma unroll
    for (int mt = 0; mt < 4; mt++)
#pragma unroll
        for (int nt = 0; nt < 4; nt++)
#pragma unroll
            for (int i = 0; i < 4; i++) acc[mt][nt][i] = 0.f;

    for (int k0 = 0; k0 < DM; k0 += 32) {
#pragma unroll
        for (int rep = 0; rep < 4; rep++) {
            const int rr = lr + 32 * rep;
            float4 av = *(const float4*)(Ag + (size_t)(32 * rep) * DM + k0);
            float4 wv = *(const float4*)(Wg + (size_t)(32 * rep) * DM + k0);
            As[lc + 0][rr] = f2tf(av.x); As[lc + 1][rr] = f2tf(av.y);
            As[lc + 2][rr] = f2tf(av.z); As[lc + 3][rr] = f2tf(av.w);
            Ws[lc + 0][rr] = f2tf(wv.x); Ws[lc + 1][rr] = f2tf(wv.y);
            Ws[lc + 2][rr] = f2tf(wv.z); Ws[lc + 3][rr] = f2tf(wv.w);
        }
        __syncthreads();

#pragma unroll
        for (int kk = 0; kk < 32; kk += 8) {
            uint32_t bf[4][2];
#pragma unroll
            for (int nt = 0; nt < 4; nt++) {
                bf[nt][0] = Ws[kk + t][wn + nt * 8 + g];
                bf[nt][1] = Ws[kk + t + 4][wn + nt * 8 + g];
            }
#pragma unroll
            for (int mt = 0; mt < 4; mt++) {
                const int m0 = wm + mt * 16;
                uint32_t a0 = As[kk + t][m0 + g];
                uint32_t a1 = As[kk + t][m0 + g + 8];
                uint32_t a2 = As[kk + t + 4][m0 + g];
                uint32_t a3 = As[kk + t + 4][m0 + g + 8];
#pragma unroll
                for (int nt = 0; nt < 4; nt++)
                    mma_tf32(acc[mt][nt], a0, a1, a2, a3, bf[nt][0], bf[nt][1]);
            }
        }
        __syncthreads();
    }

#pragma unroll
    for (int mt = 0; mt < 4; mt++) {
        const int row0 = bm + wm + mt * 16 + g;
#pragma unroll
        for (int nt = 0; nt < 4; nt++) {
            const int col = bn + wn + nt * 8 + 2 * t;
            const float bv0 = bias[col], bv1 = bias[col + 1];
            float2 r0 = make_float2(acc[mt][nt][0] + bv0, acc[mt][nt][1] + bv1);
            float2 r1 = make_float2(acc[mt][nt][2] + bv0, acc[mt][nt][3] + bv1);
            *(float2*)&C[(size_t)row0 * DM + col]       = r0;
            *(float2*)&C[(size_t)(row0 + 8) * DM + col] = r1;
        }
    }
}

// ---------------------------------------------------------------------------
// Tensor-core flash attention (tf32 mma). One block = one (b,h) x 64 q-rows.
// 128 threads = 4 warps; each warp owns 16 q-rows (m16), all 64 keys/dims (8 n8).
// Q fragments resident in registers; P stays in register fragments, converted
// C-frag -> A-frag layout via warp shuffles (no smem round-trip).
// ---------------------------------------------------------------------------
__global__ void __launch_bounds__(128) attn_tf32(
    const float* __restrict__ qp, const float* __restrict__ kp,
    const float* __restrict__ vp, const int* __restrict__ mask,
    float* __restrict__ ctx)
{
    __shared__ uint32_t Ks[64][68];   // also used to stage Q in the prologue
    __shared__ uint32_t Vs[64][72];
    __shared__ float    mk[64];

    const int tid  = threadIdx.x;
    const int lane = tid & 31;
    const int wq   = tid >> 5;        // warp -> q-row group (0..3)
    const int g    = lane >> 2;
    const int t    = lane & 3;

    const int bh = blockIdx.y;
    const int b  = bh >> 4;
    const int h  = bh & 15;
    const int q0 = blockIdx.x * 64;

    const int r  = tid & 63;            // staging row
    const int cb = (tid >> 6) << 5;     // staging col base: 0 or 32

    // ---- stage Q (pre-scaled) into Ks, extract register fragments ----
    {
        const float* qg = qp + (size_t)(b * TSEQ + q0 + r) * DM + h * DK + cb;
#pragma unroll
        for (int c = 0; c < 32; c += 4) {
            float4 v = *(const float4*)(qg + c);
            Ks[r][cb + c + 0] = f2tf(v.x * 0.125f);
            Ks[r][cb + c + 1] = f2tf(v.y * 0.125f);
            Ks[r][cb + c + 2] = f2tf(v.z * 0.125f);
            Ks[r][cb + c + 3] = f2tf(v.w * 0.125f);
        }
    }
    __syncthreads();

    uint32_t qf[8][4];
#pragma unroll
    for (int ks = 0; ks < 8; ks++) {
        const int kk = ks * 8;
        qf[ks][0] = Ks[wq * 16 + g][kk + t];
        qf[ks][1] = Ks[wq * 16 + g + 8][kk + t];
        qf[ks][2] = Ks[wq * 16 + g][kk + t + 4];
        qf[ks][3] = Ks[wq * 16 + g + 8][kk + t + 4];
    }
    __syncthreads();   // all warps done reading Q before Ks is reused for K

    float of[8][4];
#pragma unroll
    for (int nt = 0; nt < 8; nt++)
#pragma unroll
        for (int i = 0; i < 4; i++) of[nt][i] = 0.f;
    float m0 = -1e30f, m1 = -1e30f, l0 = 0.f, l1 = 0.f;

    const float* kg = kp + (size_t)b * TSEQ * DM + h * DK;
    const float* vg = vp + (size_t)b * TSEQ * DM + h * DK;
    const int*   mg = mask + b * TSEQ;

    for (int j0 = 0; j0 < TSEQ; j0 += 64) {
        // ---- stage K (64x64) and V (64x64) ----
        const float* ksrc = kg + (size_t)(j0 + r) * DM + cb;
        const float* vsrc = vg + (size_t)(j0 + r) * DM + cb;
#pragma unroll
        for (int c = 0; c < 32; c += 4) {
            float4 kv = *(const float4*)(ksrc + c);
            Ks[r][cb + c + 0] = f2tf(kv.x); Ks[r][cb + c + 1] = f2tf(kv.y);
            Ks[r][cb + c + 2] = f2tf(kv.z); Ks[r][cb + c + 3] = f2tf(kv.w);
            float4 vv = *(const float4*)(vsrc + c);
            Vs[r][cb + c + 0] = f2tf(vv.x); Vs[r][cb + c + 1] = f2tf(vv.y);
            Vs[r][cb + c + 2] = f2tf(vv.z); Vs[r][cb + c + 3] = f2tf(vv.w);
        }
        if (tid < 64) mk[tid] = (mg[j0 + tid] == 0) ? -1e30f : 0.f;
        __syncthreads();

        // ---- S = (Q*scale) @ K^T ----
        float sf[8][4];
#pragma unroll
        for (int nt = 0; nt < 8; nt++)
#pragma unroll
            for (int i = 0; i < 4; i++) sf[nt][i] = 0.f;

#pragma unroll
        for (int ks = 0; ks < 8; ks++) {
            const int kk = ks * 8;
#pragma unroll
            for (int nt = 0; nt < 8; nt++) {
                uint32_t b0 = Ks[nt * 8 + g][kk + t];
                uint32_t b1 = Ks[nt * 8 + g][kk + t + 4];
                mma_tf32(sf[nt], qf[ks][0], qf[ks][1], qf[ks][2], qf[ks][3], b0, b1);
            }
        }

        // ---- mask + online softmax on fragments ----
        float mn0 = m0, mn1 = m1;
#pragma unroll
        for (int nt = 0; nt < 8; nt++) {
            const float a0 = mk[nt * 8 + 2 * t];
            const float a1 = mk[nt * 8 + 2 * t + 1];
            sf[nt][0] += a0; sf[nt][1] += a1;
            sf[nt][2] += a0; sf[nt][3] += a1;
            mn0 = fmaxf(mn0, fmaxf(sf[nt][0], sf[nt][1]));
            mn1 = fmaxf(mn1, fmaxf(sf[nt][2], sf[nt][3]));
        }
        mn0 = fmaxf(mn0, __shfl_xor_sync(0xffffffffu, mn0, 1));
        mn0 = fmaxf(mn0, __shfl_xor_sync(0xffffffffu, mn0, 2));
        mn1 = fmaxf(mn1, __shfl_xor_sync(0xffffffffu, mn1, 1));
        mn1 = fmaxf(mn1, __shfl_xor_sync(0xffffffffu, mn1, 2));

        const float corr0 = __expf(m0 - mn0);
        const float corr1 = __expf(m1 - mn1);
        m0 = mn0; m1 = mn1;

        float rs0 = 0.f, rs1 = 0.f;
#pragma unroll
        for (int nt = 0; nt < 8; nt++) {
            sf[nt][0] = __expf(sf[nt][0] - m0);
            sf[nt][1] = __expf(sf[nt][1] - m0);
            sf[nt][2] = __expf(sf[nt][2] - m1);
            sf[nt][3] = __expf(sf[nt][3] - m1);
            rs0 += sf[nt][0] + sf[nt][1];
            rs1 += sf[nt][2] + sf[nt][3];
            of[nt][0] *= corr0; of[nt][1] *= corr0;
            of[nt][2] *= corr1; of[nt][3] *= corr1;
        }
        rs0 += __shfl_xor_sync(0xffffffffu, rs0, 1);
        rs0 += __shfl_xor_sync(0xffffffffu, rs0, 2);
        rs1 += __shfl_xor_sync(0xffffffffu, rs1, 1);
        rs1 += __shfl_xor_sync(0xffffffffu, rs1, 2);
        l0 = l0 * corr0 + rs0;
        l1 = l1 * corr1 + rs1;

        // ---- O += P @ V : convert P C-frag -> A-frag via shuffles ----
        const int srcA = (lane & 28) | (t >> 1);
        const int srcC = srcA + 2;
        const bool odd = (t & 1);
#pragma unroll
        for (int ks = 0; ks < 8; ks++) {
            float v00 = __shfl_sync(0xffffffffu, sf[ks][0], srcA);
            float v01 = __shfl_sync(0xffffffffu, sf[ks][1], srcA);
            float v10 = __shfl_sync(0xffffffffu, sf[ks][2], srcA);
            float v11 = __shfl_sync(0xffffffffu, sf[ks][3], srcA);
            float w00 = __shfl_sync(0xffffffffu, sf[ks][0], srcC);
            float w01 = __shfl_sync(0xffffffffu, sf[ks][1], srcC);
            float w10 = __shfl_sync(0xffffffffu, sf[ks][2], srcC);
            float w11 = __shfl_sync(0xffffffffu, sf[ks][3], srcC);
            uint32_t a0 = f2tf(odd ? v01 : v00);
            uint32_t a1 = f2tf(odd ? v11 : v10);
            uint32_t a2 = f2tf(odd ? w01 : w00);
            uint32_t a3 = f2tf(odd ? w11 : w10);
            const int kk = ks * 8;
#pragma unroll
            for (int nt = 0; nt < 8; nt++) {
                uint32_t b0 = Vs[kk + t][nt * 8 + g];
                uint32_t b1 = Vs[kk + t + 4][nt * 8 + g];
                mma_tf32(of[nt], a0, a1, a2, a3, b0, b1);
            }
        }
        __syncthreads();
    }

    // ---- epilogue ----
    const float inv0 = 1.f / l0;
    const float inv1 = 1.f / l1;
    const int row0 = q0 + wq * 16 + g;
    float* d0 = ctx + (size_t)(b * TSEQ + row0) * DM + h * DK;
    float* d1 = ctx + (size_t)(b * TSEQ + row0 + 8) * DM + h * DK;
#pragma unroll
    for (int nt = 0; nt < 8; nt++) {
        const int col = nt * 8 + 2 * t;
        *(float2*)&d0[col] = make_float2(of[nt][0] * inv0, of[nt][1] * inv0);
        *(float2*)&d1[col] = make_float2(of[nt][2] * inv1, of[nt][3] * inv1);
    }
}

// ---------------------------------------------------------------------------
// Launch
// ---------------------------------------------------------------------------
extern "C" void kernel_launch(void* const* d_in, const int* in_sizes, int n_in,
                              void* d_out, int out_size)
{
    const float* Q    = (const float*)d_in[0];
    const float* Kin  = (const float*)d_in[1];
    const float* Vin  = (const float*)d_in[2];
    const int*   mask = (const int*)  d_in[3];
    const float* W_q  = (const float*)d_in[4];
    const float* b_q  = (const float*)d_in[5];
    const float* W_k  = (const float*)d_in[6];
    const float* b_k  = (const float*)d_in[7];
    const float* W_v  = (const float*)d_in[8];
    const float* b_v  = (const float*)d_in[9];
    const float* W_o  = (const float*)d_in[10];
    const float* b_o  = (const float*)d_in[11];
    float* out = (float*)d_out;

    float *qp, *kp, *vp, *ctx;
    cudaGetSymbolAddress((void**)&qp,  g_qp);
    cudaGetSymbolAddress((void**)&kp,  g_kp);
    cudaGetSymbolAddress((void**)&vp,  g_vp);
    cudaGetSymbolAddress((void**)&ctx, g_ctx);

    dim3 gg(DM / 128, BT / 128);   // (8, 64)
    gemm_tf32<<<gg, 256>>>(Q,   W_q, b_q, qp);
    gemm_tf32<<<gg, 256>>>(Kin, W_k, b_k, kp);
    gemm_tf32<<<gg, 256>>>(Vin, W_v, b_v, vp);

    attn_tf32<<<dim3(TSEQ / 64, BATCH * HEADS), 128>>>(qp, kp, vp, mask, ctx);

    gemm_tf32<<<gg, 256>>>(ctx, W_o, b_o, out);
}

// round 3
// speedup vs baseline: 9.5304x; 2.8853x over previous
#include <cuda_runtime.h>
#include <cuda_fp16.h>
#include <cstdint>

#define BATCH   4
#define TSEQ    2048
#define DM      1024
#define HEADS   16
#define DK      64
#define BT      (BATCH * TSEQ)   // 8192

// ---------------- scratch (device globals; ushort to avoid ctor issues) ----
__device__ unsigned short g_hq[BT * DM];     // fp16 copies of inputs
__device__ unsigned short g_hk[BT * DM];
__device__ unsigned short g_hv[BT * DM];
__device__ unsigned short g_hw[4][DM * DM];  // fp16 weights
__device__ unsigned short g_qp[BT * DM];     // projected q (pre-scaled), k, v
__device__ unsigned short g_kp[BT * DM];
__device__ unsigned short g_vp[BT * DM];
__device__ unsigned short g_ctx[BT * DM];    // attention output

// ---------------- ptx helpers ----------------------------------------------
__device__ __forceinline__ uint32_t smem_u32(const void* p) {
    return (uint32_t)__cvta_generic_to_shared(p);
}
__device__ __forceinline__ void ldsm4(uint32_t r[4], uint32_t a) {
    asm volatile("ldmatrix.sync.aligned.m8n8.x4.shared.b16 {%0,%1,%2,%3}, [%4];"
                 : "=r"(r[0]), "=r"(r[1]), "=r"(r[2]), "=r"(r[3]) : "r"(a));
}
__device__ __forceinline__ void ldsm4t(uint32_t r[4], uint32_t a) {
    asm volatile("ldmatrix.sync.aligned.m8n8.x4.trans.shared.b16 {%0,%1,%2,%3}, [%4];"
                 : "=r"(r[0]), "=r"(r[1]), "=r"(r[2]), "=r"(r[3]) : "r"(a));
}
__device__ __forceinline__ void mma16816(float c[4],
    uint32_t a0, uint32_t a1, uint32_t a2, uint32_t a3, uint32_t b0, uint32_t b1) {
    asm volatile(
        "mma.sync.aligned.m16n8k16.row.col.f32.f16.f16.f32 "
        "{%0,%1,%2,%3}, {%4,%5,%6,%7}, {%8,%9}, {%0,%1,%2,%3};\n"
        : "+f"(c[0]), "+f"(c[1]), "+f"(c[2]), "+f"(c[3])
        : "r"(a0), "r"(a1), "r"(a2), "r"(a3), "r"(b0), "r"(b1));
}
__device__ __forceinline__ void cp16(uint32_t s, const void* g) {
    asm volatile("cp.async.cg.shared.global [%0], [%1], 16;" :: "r"(s), "l"(g));
}
__device__ __forceinline__ void cp_commit() {
    asm volatile("cp.async.commit_group;");
}
template<int N> __device__ __forceinline__ void cp_wait() {
    asm volatile("cp.async.wait_group %0;" :: "n"(N));
}
__device__ __forceinline__ uint32_t pkh2(float x, float y) {
    __half2 h = __floats2half2_rn(x, y);
    return *reinterpret_cast<uint32_t*>(&h);
}

// ---------------- fp32 -> fp16 conversion ----------------------------------
__global__ void __launch_bounds__(256) cvt_f2h(
    const float* __restrict__ s, unsigned short* __restrict__ d)
{
    const int i = (blockIdx.x * 256 + threadIdx.x) * 8;
    float4 v0 = *(const float4*)(s + i);
    float4 v1 = *(const float4*)(s + i + 4);
    __half2 h0 = __floats2half2_rn(v0.x, v0.y);
    __half2 h1 = __floats2half2_rn(v0.z, v0.w);
    __half2 h2 = __floats2half2_rn(v1.x, v1.y);
    __half2 h3 = __floats2half2_rn(v1.z, v1.w);
    uint4 u;
    u.x = *(uint32_t*)&h0; u.y = *(uint32_t*)&h1;
    u.z = *(uint32_t*)&h2; u.w = *(uint32_t*)&h3;
    *(uint4*)(d + i) = u;
}

// ---------------- GEMM: C[M,1024] = A @ W^T, fp16 in, fp32 acc --------------
// 128x128 block tile, BK=32, 256 threads (8 warps = 2m x 4n), warp 64x32.
// cp.async double-buffered; ldmatrix fragments; epilogue (acc+bias)*scale.
template<bool OUT_HALF>
__global__ void __launch_bounds__(256) gemm_h(
    const __half* __restrict__ A, const __half* __restrict__ W,
    const float* __restrict__ bias, void* __restrict__ Cv, float scale)
{
    __shared__ __half As[2][128][40];
    __shared__ __half Ws[2][128][40];

    const int tid = threadIdx.x, lane = tid & 31, wid = tid >> 5;
    const int g = lane >> 2, t = lane & 3;
    const int wm = (wid >> 2) * 64, wn = (wid & 3) * 32;
    const int bm = blockIdx.y * 128, bn = blockIdx.x * 128;

    const int r0 = tid >> 2;               // rows 0..63
    const int r1 = 64 + r0;                // rows 64..127
    const int o0 = (tid & 3) * 8;          // half offset within row

    const __half* Ag = A + (size_t)bm * DM;
    const __half* Wg = W + (size_t)bn * DM;

    float acc[4][4][4] = {};

    auto stage = [&](int buf, int k0) {
        cp16(smem_u32(&As[buf][r0][o0]), Ag + (size_t)r0 * DM + k0 + o0);
        cp16(smem_u32(&As[buf][r1][o0]), Ag + (size_t)r1 * DM + k0 + o0);
        cp16(smem_u32(&Ws[buf][r0][o0]), Wg + (size_t)r0 * DM + k0 + o0);
        cp16(smem_u32(&Ws[buf][r1][o0]), Wg + (size_t)r1 * DM + k0 + o0);
    };

    stage(0, 0); cp_commit();

    const int lrow = lane & 15, lcol = (lane >> 4) * 8;

    for (int kt = 0; kt < 32; kt++) {
        const int cur = kt & 1;
        if (kt < 31) { stage(cur ^ 1, (kt + 1) * 32); cp_commit(); cp_wait<1>(); }
        else         { cp_wait<0>(); }
        __syncthreads();

#pragma unroll
        for (int kk = 0; kk < 2; kk++) {
            uint32_t a[4][4], bf[2][4];
#pragma unroll
            for (int mt = 0; mt < 4; mt++)
                ldsm4(a[mt], smem_u32(&As[cur][wm + mt * 16 + lrow][kk * 16 + lcol]));
#pragma unroll
            for (int ng = 0; ng < 2; ng++)
                ldsm4(bf[ng], smem_u32(&Ws[cur][wn + ng * 16 + lrow][kk * 16 + lcol]));
#pragma unroll
            for (int mt = 0; mt < 4; mt++)
#pragma unroll
                for (int nt = 0; nt < 4; nt++) {
                    const uint32_t b0 = (nt & 1) ? bf[nt >> 1][1] : bf[nt >> 1][0];
                    const uint32_t b1 = (nt & 1) ? bf[nt >> 1][3] : bf[nt >> 1][2];
                    mma16816(acc[mt][nt], a[mt][0], a[mt][1], a[mt][2], a[mt][3], b0, b1);
                }
        }
        __syncthreads();
    }

#pragma unroll
    for (int nt = 0; nt < 4; nt++) {
        const int col = bn + wn + nt * 8 + 2 * t;
        const float bb0 = bias[col], bb1 = bias[col + 1];
#pragma unroll
        for (int mt = 0; mt < 4; mt++) {
            const int row = bm + wm + mt * 16 + g;
            const float x0 = (acc[mt][nt][0] + bb0) * scale;
            const float x1 = (acc[mt][nt][1] + bb1) * scale;
            const float x2 = (acc[mt][nt][2] + bb0) * scale;
            const float x3 = (acc[mt][nt][3] + bb1) * scale;
            if (OUT_HALF) {
                __half* C = (__half*)Cv;
                *(__half2*)(C + (size_t)row * DM + col)       = __floats2half2_rn(x0, x1);
                *(__half2*)(C + (size_t)(row + 8) * DM + col) = __floats2half2_rn(x2, x3);
            } else {
                float* C = (float*)Cv;
                *(float2*)(C + (size_t)row * DM + col)       = make_float2(x0, x1);
                *(float2*)(C + (size_t)(row + 8) * DM + col) = make_float2(x2, x3);
            }
        }
    }
}

// ---------------- fp16 flash attention --------------------------------------
// Block = one (b,h) x 128 q-rows, 256 threads (8 warps x 16 rows).
// K/V tiles of 64 keys double-buffered via cp.async; ldmatrix fragments;
// fp16 P needs no layout shuffles (half2 pack of C-frag == A-frag).
// Q comes in pre-scaled by 1/8 from the projection epilogue.
__global__ void __launch_bounds__(256) attn_h(
    const __half* __restrict__ qp, const __half* __restrict__ kp,
    const __half* __restrict__ vp, const int* __restrict__ mask,
    __half* __restrict__ ctx)
{
    __shared__ __half Ks[2][64][72];
    __shared__ __half Vs[2][64][72];
    __shared__ int    Msk[2][64];

    const int tid = threadIdx.x, lane = tid & 31, wq = tid >> 5;
    const int g = lane >> 2, t = lane & 3;
    const int bh = blockIdx.y, b = bh >> 4, h = bh & 15;
    const int q0 = blockIdx.x * 128;

    const __half* kg = kp + (size_t)b * TSEQ * DM + h * DK;
    const __half* vg = vp + (size_t)b * TSEQ * DM + h * DK;
    const int*    mg = mask + b * TSEQ;

    // Q fragments straight from global (one-time)
    uint32_t qf[4][4];
    {
        const __half* qb  = qp + (size_t)(b * TSEQ + q0 + wq * 16) * DM + h * DK;
        const __half* qr0 = qb + (size_t)g * DM + 2 * t;
        const __half* qr1 = qb + (size_t)(g + 8) * DM + 2 * t;
#pragma unroll
        for (int ks = 0; ks < 4; ks++) {
            qf[ks][0] = *(const uint32_t*)(qr0 + ks * 16);
            qf[ks][1] = *(const uint32_t*)(qr1 + ks * 16);
            qf[ks][2] = *(const uint32_t*)(qr0 + ks * 16 + 8);
            qf[ks][3] = *(const uint32_t*)(qr1 + ks * 16 + 8);
        }
    }

    const int sr0 = tid >> 3;            // rows 0..31
    const int sr1 = 32 + sr0;            // rows 32..63
    const int so  = (tid & 7) * 8;

    auto stage = [&](int buf, int j0) {
        cp16(smem_u32(&Ks[buf][sr0][so]), kg + (size_t)(j0 + sr0) * DM + so);
        cp16(smem_u32(&Ks[buf][sr1][so]), kg + (size_t)(j0 + sr1) * DM + so);
        cp16(smem_u32(&Vs[buf][sr0][so]), vg + (size_t)(j0 + sr0) * DM + so);
        cp16(smem_u32(&Vs[buf][sr1][so]), vg + (size_t)(j0 + sr1) * DM + so);
        if (tid < 16) cp16(smem_u32(&Msk[buf][tid * 4]), mg + j0 + tid * 4);
    };

    float of[8][4] = {};
    float m0 = -1e30f, m1 = -1e30f, l0 = 0.f, l1 = 0.f;

    stage(0, 0); cp_commit();

    const int lrow = lane & 15, lcol = (lane >> 4) * 8;

    for (int jt = 0; jt < 32; jt++) {
        const int cur = jt & 1;
        if (jt < 31) { stage(cur ^ 1, (jt + 1) * 64); cp_commit(); cp_wait<1>(); }
        else         { cp_wait<0>(); }
        __syncthreads();

        // ---- S = Q @ K^T (Q pre-scaled) ----
        float sf[8][4] = {};
#pragma unroll
        for (int ks = 0; ks < 4; ks++)
#pragma unroll
            for (int ng = 0; ng < 4; ng++) {
                uint32_t kb[4];
                ldsm4(kb, smem_u32(&Ks[cur][ng * 16 + lrow][ks * 16 + lcol]));
                mma16816(sf[2 * ng],     qf[ks][0], qf[ks][1], qf[ks][2], qf[ks][3], kb[0], kb[2]);
                mma16816(sf[2 * ng + 1], qf[ks][0], qf[ks][1], qf[ks][2], qf[ks][3], kb[1], kb[3]);
            }

        // ---- mask + online softmax ----
        float mn0 = m0, mn1 = m1;
#pragma unroll
        for (int nt = 0; nt < 8; nt++) {
            const float a0 = Msk[cur][nt * 8 + 2 * t]     ? 0.f : -1e30f;
            const float a1 = Msk[cur][nt * 8 + 2 * t + 1] ? 0.f : -1e30f;
            sf[nt][0] += a0; sf[nt][1] += a1;
            sf[nt][2] += a0; sf[nt][3] += a1;
            mn0 = fmaxf(mn0, fmaxf(sf[nt][0], sf[nt][1]));
            mn1 = fmaxf(mn1, fmaxf(sf[nt][2], sf[nt][3]));
        }
        mn0 = fmaxf(mn0, __shfl_xor_sync(0xffffffffu, mn0, 1));
        mn0 = fmaxf(mn0, __shfl_xor_sync(0xffffffffu, mn0, 2));
        mn1 = fmaxf(mn1, __shfl_xor_sync(0xffffffffu, mn1, 1));
        mn1 = fmaxf(mn1, __shfl_xor_sync(0xffffffffu, mn1, 2));

        const float c0 = __expf(m0 - mn0), c1 = __expf(m1 - mn1);
        m0 = mn0; m1 = mn1;

        float rs0 = 0.f, rs1 = 0.f;
#pragma unroll
        for (int nt = 0; nt < 8; nt++) {
            sf[nt][0] = __expf(sf[nt][0] - m0);
            sf[nt][1] = __expf(sf[nt][1] - m0);
            sf[nt][2] = __expf(sf[nt][2] - m1);
            sf[nt][3] = __expf(sf[nt][3] - m1);
            rs0 += sf[nt][0] + sf[nt][1];
            rs1 += sf[nt][2] + sf[nt][3];
            of[nt][0] *= c0; of[nt][1] *= c0;
            of[nt][2] *= c1; of[nt][3] *= c1;
        }
        rs0 += __shfl_xor_sync(0xffffffffu, rs0, 1);
        rs0 += __shfl_xor_sync(0xffffffffu, rs0, 2);
        rs1 += __shfl_xor_sync(0xffffffffu, rs1, 1);
        rs1 += __shfl_xor_sync(0xffffffffu, rs1, 2);
        l0 = l0 * c0 + rs0;
        l1 = l1 * c1 + rs1;

        // ---- O += P @ V ----
#pragma unroll
        for (int kq = 0; kq < 4; kq++) {
            const uint32_t a0 = pkh2(sf[2 * kq][0],     sf[2 * kq][1]);
            const uint32_t a1 = pkh2(sf[2 * kq][2],     sf[2 * kq][3]);
            const uint32_t a2 = pkh2(sf[2 * kq + 1][0], sf[2 * kq + 1][1]);
            const uint32_t a3 = pkh2(sf[2 * kq + 1][2], sf[2 * kq + 1][3]);
#pragma unroll
            for (int dg = 0; dg < 4; dg++) {
                uint32_t vb[4];
                ldsm4t(vb, smem_u32(&Vs[cur][kq * 16 + lrow][dg * 16 + lcol]));
                mma16816(of[2 * dg],     a0, a1, a2, a3, vb[0], vb[1]);
                mma16816(of[2 * dg + 1], a0, a1, a2, a3, vb[2], vb[3]);
            }
        }
        __syncthreads();
    }

    // ---- epilogue ----
    const float i0 = 1.f / l0, i1 = 1.f / l1;
    __half* d0 = ctx + (size_t)(b * TSEQ + q0 + wq * 16 + g) * DM + h * DK;
    __half* d1 = d0 + (size_t)8 * DM;
#pragma unroll
    for (int nt = 0; nt < 8; nt++) {
        const int col = nt * 8 + 2 * t;
        *(__half2*)(d0 + col) = __floats2half2_rn(of[nt][0] * i0, of[nt][1] * i0);
        *(__half2*)(d1 + col) = __floats2half2_rn(of[nt][2] * i1, of[nt][3] * i1);
    }
}

// ---------------- launch -----------------------------------------------------
extern "C" void kernel_launch(void* const* d_in, const int* in_sizes, int n_in,
                              void* d_out, int out_size)
{
    const float* Q    = (const float*)d_in[0];
    const float* Kin  = (const float*)d_in[1];
    const float* Vin  = (const float*)d_in[2];
    const int*   mask = (const int*)  d_in[3];
    const float* W_q  = (const float*)d_in[4];
    const float* b_q  = (const float*)d_in[5];
    const float* W_k  = (const float*)d_in[6];
    const float* b_k  = (const float*)d_in[7];
    const float* W_v  = (const float*)d_in[8];
    const float* b_v  = (const float*)d_in[9];
    const float* W_o  = (const float*)d_in[10];
    const float* b_o  = (const float*)d_in[11];
    float* out = (float*)d_out;

    unsigned short *hq, *hk, *hv, *hw, *qp, *kp, *vp, *ctx;
    cudaGetSymbolAddress((void**)&hq,  g_hq);
    cudaGetSymbolAddress((void**)&hk,  g_hk);
    cudaGetSymbolAddress((void**)&hv,  g_hv);
    cudaGetSymbolAddress((void**)&hw,  g_hw);
    cudaGetSymbolAddress((void**)&qp,  g_qp);
    cudaGetSymbolAddress((void**)&kp,  g_kp);
    cudaGetSymbolAddress((void**)&vp,  g_vp);
    cudaGetSymbolAddress((void**)&ctx, g_ctx);

    const int nIn = BT * DM;      // 8388608
    const int nW  = DM * DM;      // 1048576
    cvt_f2h<<<nIn / 8 / 256, 256>>>(Q,   hq);
    cvt_f2h<<<nIn / 8 / 256, 256>>>(Kin, hk);
    cvt_f2h<<<nIn / 8 / 256, 256>>>(Vin, hv);
    cvt_f2h<<<nW / 8 / 256, 256>>>(W_q, hw + 0 * (size_t)nW);
    cvt_f2h<<<nW / 8 / 256, 256>>>(W_k, hw + 1 * (size_t)nW);
    cvt_f2h<<<nW / 8 / 256, 256>>>(W_v, hw + 2 * (size_t)nW);
    cvt_f2h<<<nW / 8 / 256, 256>>>(W_o, hw + 3 * (size_t)nW);

    dim3 gg(DM / 128, BT / 128);   // (8, 64)
    gemm_h<true><<<gg, 256>>>((const __half*)hq, (const __half*)(hw + 0 * (size_t)nW), b_q, qp, 0.125f);
    gemm_h<true><<<gg, 256>>>((const __half*)hk, (const __half*)(hw + 1 * (size_t)nW), b_k, kp, 1.0f);
    gemm_h<true><<<gg, 256>>>((const __half*)hv, (const __half*)(hw + 2 * (size_t)nW), b_v, vp, 1.0f);

    attn_h<<<dim3(TSEQ / 128, BATCH * HEADS), 256>>>(
        (const __half*)qp, (const __half*)kp, (const __half*)vp, mask, (__half*)ctx);

    gemm_h<false><<<gg, 256>>>((const __half*)ctx, (const __half*)(hw + 3 * (size_t)nW), b_o, out, 1.0f);
}

// round 5
// speedup vs baseline: 14.4338x; 1.5145x over previous
#include <cuda_runtime.h>
#include <cuda_fp16.h>
#include <cstdint>

#define BATCH   4
#define TSEQ    2048
#define DM      1024
#define HEADS   16
#define DK      64
#define BT      (BATCH * TSEQ)   // 8192

// ---------------- scratch (device globals) ----------------------------------
__device__ unsigned short g_hq[BT * DM];     // fp16 Q input
__device__ unsigned short g_hkc[BT * DM];    // fp16 K input, mask-compacted rows
__device__ unsigned short g_hvc[BT * DM];    // fp16 V input, mask-compacted rows
__device__ unsigned short g_hw[4][DM * DM];  // fp16 weights
__device__ unsigned short g_qp[BT * DM];     // projected q (pre-scaled by 1/8)
__device__ unsigned short g_kp[BT * DM];     // projected k (compacted)
__device__ unsigned short g_vp[BT * DM];     // projected v (compacted)
__device__ unsigned short g_ctx[BT * DM];    // attention output
__device__ int g_idx[BATCH * TSEQ];          // valid key indices per batch
__device__ int g_cnt[BATCH];                 // valid key counts

// ---------------- ptx helpers ------------------------------------------------
__device__ __forceinline__ uint32_t smem_u32(const void* p) {
    return (uint32_t)__cvta_generic_to_shared(p);
}
__device__ __forceinline__ void ldsm4(uint32_t r[4], uint32_t a) {
    asm volatile("ldmatrix.sync.aligned.m8n8.x4.shared.b16 {%0,%1,%2,%3}, [%4];"
                 : "=r"(r[0]), "=r"(r[1]), "=r"(r[2]), "=r"(r[3]) : "r"(a));
}
__device__ __forceinline__ void ldsm4t(uint32_t r[4], uint32_t a) {
    asm volatile("ldmatrix.sync.aligned.m8n8.x4.trans.shared.b16 {%0,%1,%2,%3}, [%4];"
                 : "=r"(r[0]), "=r"(r[1]), "=r"(r[2]), "=r"(r[3]) : "r"(a));
}
__device__ __forceinline__ void mma16816(float c[4],
    uint32_t a0, uint32_t a1, uint32_t a2, uint32_t a3, uint32_t b0, uint32_t b1) {
    asm volatile(
        "mma.sync.aligned.m16n8k16.row.col.f32.f16.f16.f32 "
        "{%0,%1,%2,%3}, {%4,%5,%6,%7}, {%8,%9}, {%0,%1,%2,%3};\n"
        : "+f"(c[0]), "+f"(c[1]), "+f"(c[2]), "+f"(c[3])
        : "r"(a0), "r"(a1), "r"(a2), "r"(a3), "r"(b0), "r"(b1));
}
__device__ __forceinline__ void cp16(uint32_t s, const void* g) {
    asm volatile("cp.async.cg.shared.global [%0], [%1], 16;" :: "r"(s), "l"(g));
}
__device__ __forceinline__ void cp_commit() {
    asm volatile("cp.async.commit_group;");
}
template<int N> __device__ __forceinline__ void cp_wait() {
    asm volatile("cp.async.wait_group %0;" :: "n"(N));
}
__device__ __forceinline__ uint32_t pkh2(float x, float y) {
    __half2 h = __floats2half2_rn(x, y);
    return *reinterpret_cast<uint32_t*>(&h);
}

// ---------------- mask compaction (deterministic prefix scan) -----------------
__global__ void __launch_bounds__(256) compact_mask(
    const int* __restrict__ mask, int* __restrict__ idx, int* __restrict__ cnt)
{
    const int b = blockIdx.x;
    const int tid = threadIdx.x, lane = tid & 31, wid = tid >> 5;
    __shared__ int wtot[8];
    __shared__ int sbase;
    if (tid == 0) sbase = 0;
    __syncthreads();

    for (int c = 0; c < TSEQ; c += 256) {
        const int i = c + tid;
        const int v = mask[b * TSEQ + i] != 0;
        const unsigned bal = __ballot_sync(0xffffffffu, v);
        if (lane == 0) wtot[wid] = __popc(bal);
        __syncthreads();
        int off = sbase;
        for (int w = 0; w < wid; w++) off += wtot[w];
        off += __popc(bal & ((1u << lane) - 1));
        if (v) idx[b * TSEQ + off] = i;
        __syncthreads();
        if (tid == 0) {
            int t = 0;
            for (int w = 0; w < 8; w++) t += wtot[w];
            sbase += t;
        }
        __syncthreads();
    }
    if (tid == 0) cnt[b] = sbase;
}

// ---------------- gather + fp32->fp16 for K and V inputs ----------------------
// One block = 2 rows (256 threads, 8 elems each). Valid rows gathered via idx;
// rows [cnt, pad128) zero-filled; rows beyond pad never touched (never read).
__global__ void __launch_bounds__(256) gather_cvt(
    const float* __restrict__ K, const float* __restrict__ V,
    const int* __restrict__ idx, const int* __restrict__ cnt,
    unsigned short* __restrict__ kc, unsigned short* __restrict__ vc)
{
    const int row = blockIdx.x * 2 + (threadIdx.x >> 7);
    const int b = row >> 11, j = row & 2047;
    const int Nb = cnt[b];
    const int pad = (Nb + 127) & ~127;
    if (j >= pad) return;
    const int e = (threadIdx.x & 127) * 8;
    const size_t dst = (size_t)row * DM + e;
    if (j < Nb) {
        const size_t src = ((size_t)(b * TSEQ) + idx[b * TSEQ + j]) * DM + e;
        float4 k0 = *(const float4*)(K + src);
        float4 k1 = *(const float4*)(K + src + 4);
        float4 v0 = *(const float4*)(V + src);
        float4 v1 = *(const float4*)(V + src + 4);
        uint4 ku, vu;
        ku.x = pkh2(k0.x, k0.y); ku.y = pkh2(k0.z, k0.w);
        ku.z = pkh2(k1.x, k1.y); ku.w = pkh2(k1.z, k1.w);
        vu.x = pkh2(v0.x, v0.y); vu.y = pkh2(v0.z, v0.w);
        vu.z = pkh2(v1.x, v1.y); vu.w = pkh2(v1.z, v1.w);
        *(uint4*)(kc + dst) = ku;
        *(uint4*)(vc + dst) = vu;
    } else {
        *(uint4*)(kc + dst) = make_uint4(0, 0, 0, 0);
        *(uint4*)(vc + dst) = make_uint4(0, 0, 0, 0);
    }
}

// ---------------- fp32 -> fp16 conversion -------------------------------------
__global__ void __launch_bounds__(256) cvt_f2h(
    const float* __restrict__ s, unsigned short* __restrict__ d)
{
    const int i = (blockIdx.x * 256 + threadIdx.x) * 8;
    float4 v0 = *(const float4*)(s + i);
    float4 v1 = *(const float4*)(s + i + 4);
    uint4 u;
    u.x = pkh2(v0.x, v0.y); u.y = pkh2(v0.z, v0.w);
    u.z = pkh2(v1.x, v1.y); u.w = pkh2(v1.z, v1.w);
    *(uint4*)(d + i) = u;
}

// ---------------- GEMM: C[M,1024] = A @ W^T, fp16 in, fp32 acc ----------------
// 128x128 block tile, BK=32, 256 threads (8 warps = 2m x 4n), warp 64x32.
// cp.async double-buffered; ldmatrix fragments; optional per-batch row early-exit
// for mask-compacted operands.
template<bool OUT_HALF>
__global__ void __launch_bounds__(256) gemm_h(
    const __half* __restrict__ A, const __half* __restrict__ W,
    const float* __restrict__ bias, void* __restrict__ Cv, float scale,
    const int* __restrict__ cnt)
{
    const int bm = blockIdx.y * 128, bn = blockIdx.x * 128;
    if (cnt) {
        const int Nb = cnt[bm >> 11];
        if ((bm & 2047) >= ((Nb + 127) & ~127)) return;
    }

    __shared__ __half As[2][128][40];
    __shared__ __half Ws[2][128][40];

    const int tid = threadIdx.x, lane = tid & 31, wid = tid >> 5;
    const int g = lane >> 2, t = lane & 3;
    const int wm = (wid >> 2) * 64, wn = (wid & 3) * 32;

    const int r0 = tid >> 2;
    const int r1 = 64 + r0;
    const int o0 = (tid & 3) * 8;

    const __half* Ag = A + (size_t)bm * DM;
    const __half* Wg = W + (size_t)bn * DM;

    float acc[4][4][4] = {};

    auto stage = [&](int buf, int k0) {
        cp16(smem_u32(&As[buf][r0][o0]), Ag + (size_t)r0 * DM + k0 + o0);
        cp16(smem_u32(&As[buf][r1][o0]), Ag + (size_t)r1 * DM + k0 + o0);
        cp16(smem_u32(&Ws[buf][r0][o0]), Wg + (size_t)r0 * DM + k0 + o0);
        cp16(smem_u32(&Ws[buf][r1][o0]), Wg + (size_t)r1 * DM + k0 + o0);
    };

    stage(0, 0); cp_commit();

    const int lrow = lane & 15, lcol = (lane >> 4) * 8;

    for (int kt = 0; kt < 32; kt++) {
        const int cur = kt & 1;
        if (kt < 31) { stage(cur ^ 1, (kt + 1) * 32); cp_commit(); cp_wait<1>(); }
        else         { cp_wait<0>(); }
        __syncthreads();

#pragma unroll
        for (int kk = 0; kk < 2; kk++) {
            uint32_t a[4][4], bf[2][4];
#pragma unroll
            for (int mt = 0; mt < 4; mt++)
                ldsm4(a[mt], smem_u32(&As[cur][wm + mt * 16 + lrow][kk * 16 + lcol]));
#pragma unroll
            for (int ng = 0; ng < 2; ng++)
                ldsm4(bf[ng], smem_u32(&Ws[cur][wn + ng * 16 + lrow][kk * 16 + lcol]));
#pragma unroll
            for (int mt = 0; mt < 4; mt++)
#pragma unroll
                for (int nt = 0; nt < 4; nt++) {
                    const uint32_t b0 = (nt & 1) ? bf[nt >> 1][1] : bf[nt >> 1][0];
                    const uint32_t b1 = (nt & 1) ? bf[nt >> 1][3] : bf[nt >> 1][2];
                    mma16816(acc[mt][nt], a[mt][0], a[mt][1], a[mt][2], a[mt][3], b0, b1);
                }
        }
        __syncthreads();
    }

#pragma unroll
    for (int nt = 0; nt < 4; nt++) {
        const int col = bn + wn + nt * 8 + 2 * t;
        const float bb0 = bias[col], bb1 = bias[col + 1];
#pragma unroll
        for (int mt = 0; mt < 4; mt++) {
            const int row = bm + wm + mt * 16 + g;
            const float x0 = (acc[mt][nt][0] + bb0) * scale;
            const float x1 = (acc[mt][nt][1] + bb1) * scale;
            const float x2 = (acc[mt][nt][2] + bb0) * scale;
            const float x3 = (acc[mt][nt][3] + bb1) * scale;
            if (OUT_HALF) {
                __half* C = (__half*)Cv;
                *(__half2*)(C + (size_t)row * DM + col)       = __floats2half2_rn(x0, x1);
                *(__half2*)(C + (size_t)(row + 8) * DM + col) = __floats2half2_rn(x2, x3);
            } else {
                float* C = (float*)Cv;
                *(float2*)(C + (size_t)row * DM + col)       = make_float2(x0, x1);
                *(float2*)(C + (size_t)(row + 8) * DM + col) = make_float2(x2, x3);
            }
        }
    }
}

// ---------------- fp16 flash attention over compacted keys --------------------
// Block = one (b,h) x 128 q-rows, 256 threads (8 warps x 16 rows).
// Keys are mask-compacted per batch; loop runs ceil(cnt[b]/64) tiles and
// validity is a register compare (key j < cnt[b]); no mask smem.
__global__ void __launch_bounds__(256) attn_h(
    const __half* __restrict__ qp, const __half* __restrict__ kp,
    const __half* __restrict__ vp, const int* __restrict__ cnt,
    __half* __restrict__ ctx)
{
    __shared__ __half Ks[2][64][72];
    __shared__ __half Vs[2][64][72];

    const int tid = threadIdx.x, lane = tid & 31, wq = tid >> 5;
    const int g = lane >> 2, t = lane & 3;
    const int bh = blockIdx.y, b = bh >> 4, h = bh & 15;
    const int q0 = blockIdx.x * 128;
    const int Nb = cnt[b];
    const int NT = (Nb + 63) >> 6;

    const __half* kg = kp + (size_t)b * TSEQ * DM + h * DK;
    const __half* vg = vp + (size_t)b * TSEQ * DM + h * DK;

    uint32_t qf[4][4];
    {
        const __half* qb  = qp + (size_t)(b * TSEQ + q0 + wq * 16) * DM + h * DK;
        const __half* qr0 = qb + (size_t)g * DM + 2 * t;
        const __half* qr1 = qb + (size_t)(g + 8) * DM + 2 * t;
#pragma unroll
        for (int ks = 0; ks < 4; ks++) {
            qf[ks][0] = *(const uint32_t*)(qr0 + ks * 16);
            qf[ks][1] = *(const uint32_t*)(qr1 + ks * 16);
            qf[ks][2] = *(const uint32_t*)(qr0 + ks * 16 + 8);
            qf[ks][3] = *(const uint32_t*)(qr1 + ks * 16 + 8);
        }
    }

    const int sr0 = tid >> 3;
    const int sr1 = 32 + sr0;
    const int so  = (tid & 7) * 8;

    auto stage = [&](int buf, int j0) {
        cp16(smem_u32(&Ks[buf][sr0][so]), kg + (size_t)(j0 + sr0) * DM + so);
        cp16(smem_u32(&Ks[buf][sr1][so]), kg + (size_t)(j0 + sr1) * DM + so);
        cp16(smem_u32(&Vs[buf][sr0][so]), vg + (size_t)(j0 + sr0) * DM + so);
        cp16(smem_u32(&Vs[buf][sr1][so]), vg + (size_t)(j0 + sr1) * DM + so);
    };

    float of[8][4] = {};
    float m0 = -1e30f, m1 = -1e30f, l0 = 0.f, l1 = 0.f;

    stage(0, 0); cp_commit();

    const int lrow = lane & 15, lcol = (lane >> 4) * 8;

    for (int jt = 0; jt < NT; jt++) {
        const int cur = jt & 1;
        if (jt < NT - 1) { stage(cur ^ 1, (jt + 1) * 64); cp_commit(); cp_wait<1>(); }
        else             { cp_wait<0>(); }
        __syncthreads();

        float sf[8][4] = {};
#pragma unroll
        for (int ks = 0; ks < 4; ks++)
#pragma unroll
            for (int ng = 0; ng < 4; ng++) {
                uint32_t kb[4];
                ldsm4(kb, smem_u32(&Ks[cur][ng * 16 + lrow][ks * 16 + lcol]));
                mma16816(sf[2 * ng],     qf[ks][0], qf[ks][1], qf[ks][2], qf[ks][3], kb[0], kb[2]);
                mma16816(sf[2 * ng + 1], qf[ks][0], qf[ks][1], qf[ks][2], qf[ks][3], kb[1], kb[3]);
            }

        const int jb = jt * 64 + 2 * t;
        float mn0 = m0, mn1 = m1;
#pragma unroll
        for (int nt = 0; nt < 8; nt++) {
            const float a0 = (jb + nt * 8)     < Nb ? 0.f : -1e30f;
            const float a1 = (jb + nt * 8 + 1) < Nb ? 0.f : -1e30f;
            sf[nt][0] += a0; sf[nt][1] += a1;
            sf[nt][2] += a0; sf[nt][3] += a1;
            mn0 = fmaxf(mn0, fmaxf(sf[nt][0], sf[nt][1]));
            mn1 = fmaxf(mn1, fmaxf(sf[nt][2], sf[nt][3]));
        }
        mn0 = fmaxf(mn0, __shfl_xor_sync(0xffffffffu, mn0, 1));
        mn0 = fmaxf(mn0, __shfl_xor_sync(0xffffffffu, mn0, 2));
        mn1 = fmaxf(mn1, __shfl_xor_sync(0xffffffffu, mn1, 1));
        mn1 = fmaxf(mn1, __shfl_xor_sync(0xffffffffu, mn1, 2));

        const float c0 = __expf(m0 - mn0), c1 = __expf(m1 - mn1);
        m0 = mn0; m1 = mn1;

        float rs0 = 0.f, rs1 = 0.f;
#pragma unroll
        for (int nt = 0; nt < 8; nt++) {
            sf[nt][0] = __expf(sf[nt][0] - m0);
            sf[nt][1] = __expf(sf[nt][1] - m0);
            sf[nt][2] = __expf(sf[nt][2] - m1);
            sf[nt][3] = __expf(sf[nt][3] - m1);
            rs0 += sf[nt][0] + sf[nt][1];
            rs1 += sf[nt][2] + sf[nt][3];
            of[nt][0] *= c0; of[nt][1] *= c0;
            of[nt][2] *= c1; of[nt][3] *= c1;
        }
        rs0 += __shfl_xor_sync(0xffffffffu, rs0, 1);
        rs0 += __shfl_xor_sync(0xffffffffu, rs0, 2);
        rs1 += __shfl_xor_sync(0xffffffffu, rs1, 1);
        rs1 += __shfl_xor_sync(0xffffffffu, rs1, 2);
        l0 = l0 * c0 + rs0;
        l1 = l1 * c1 + rs1;

#pragma unroll
        for (int kq = 0; kq < 4; kq++) {
            const uint32_t a0 = pkh2(sf[2 * kq][0],     sf[2 * kq][1]);
            const uint32_t a1 = pkh2(sf[2 * kq][2],     sf[2 * kq][3]);
            const uint32_t a2 = pkh2(sf[2 * kq + 1][0], sf[2 * kq + 1][1]);
            const uint32_t a3 = pkh2(sf[2 * kq + 1][2], sf[2 * kq + 1][3]);
#pragma unroll
            for (int dg = 0; dg < 4; dg++) {
                uint32_t vb[4];
                ldsm4t(vb, smem_u32(&Vs[cur][kq * 16 + lrow][dg * 16 + lcol]));
                mma16816(of[2 * dg],     a0, a1, a2, a3, vb[0], vb[1]);
                mma16816(of[2 * dg + 1], a0, a1, a2, a3, vb[2], vb[3]);
            }
        }
        __syncthreads();
    }

    const float i0 = 1.f / l0, i1 = 1.f / l1;
    __half* d0 = ctx + (size_t)(b * TSEQ + q0 + wq * 16 + g) * DM + h * DK;
    __half* d1 = d0 + (size_t)8 * DM;
#pragma unroll
    for (int nt = 0; nt < 8; nt++) {
        const int col = nt * 8 + 2 * t;
        *(__half2*)(d0 + col) = __floats2half2_rn(of[nt][0] * i0, of[nt][1] * i0);
        *(__half2*)(d1 + col) = __floats2half2_rn(of[nt][2] * i1, of[nt][3] * i1);
    }
}

// ---------------- launch --------------------------------------------------------
extern "C" void kernel_launch(void* const* d_in, const int* in_sizes, int n_in,
                              void* d_out, int out_size)
{
    const float* Q    = (const float*)d_in[0];
    const float* Kin  = (const float*)d_in[1];
    const float* Vin  = (const float*)d_in[2];
    const int*   mask = (const int*)  d_in[3];
    const float* W_q  = (const float*)d_in[4];
    const float* b_q  = (const float*)d_in[5];
    const float* W_k  = (const float*)d_in[6];
    const float* b_k  = (const float*)d_in[7];
    const float* W_v  = (const float*)d_in[8];
    const float* b_v  = (const float*)d_in[9];
    const float* W_o  = (const float*)d_in[10];
    const float* b_o  = (const float*)d_in[11];
    float* out = (float*)d_out;

    unsigned short *hq, *hkc, *hvc, *hw, *qp, *kp, *vp, *ctx;
    int *idx, *cnt;
    cudaGetSymbolAddress((void**)&hq,  g_hq);
    cudaGetSymbolAddress((void**)&hkc, g_hkc);
    cudaGetSymbolAddress((void**)&hvc, g_hvc);
    cudaGetSymbolAddress((void**)&hw,  g_hw);
    cudaGetSymbolAddress((void**)&qp,  g_qp);
    cudaGetSymbolAddress((void**)&kp,  g_kp);
    cudaGetSymbolAddress((void**)&vp,  g_vp);
    cudaGetSymbolAddress((void**)&ctx, g_ctx);
    cudaGetSymbolAddress((void**)&idx, g_idx);
    cudaGetSymbolAddress((void**)&cnt, g_cnt);

    const int nIn = BT * DM;      // 8388608
    const int nW  = DM * DM;      // 1048576

    compact_mask<<<BATCH, 256>>>(mask, idx, cnt);
    cvt_f2h<<<nIn / 8 / 256, 256>>>(Q, hq);
    cvt_f2h<<<nW / 8 / 256, 256>>>(W_q, hw + 0 * (size_t)nW);
    cvt_f2h<<<nW / 8 / 256, 256>>>(W_k, hw + 1 * (size_t)nW);
    cvt_f2h<<<nW / 8 / 256, 256>>>(W_v, hw + 2 * (size_t)nW);
    cvt_f2h<<<nW / 8 / 256, 256>>>(W_o, hw + 3 * (size_t)nW);
    gather_cvt<<<BT / 2, 256>>>(Kin, Vin, idx, cnt, hkc, hvc);

    dim3 gg(DM / 128, BT / 128);   // (8, 64)
    gemm_h<true><<<gg, 256>>>((const __half*)hq,  (const __half*)(hw + 0 * (size_t)nW), b_q, qp, 0.125f, nullptr);
    gemm_h<true><<<gg, 256>>>((const __half*)hkc, (const __half*)(hw + 1 * (size_t)nW), b_k, kp, 1.0f, cnt);
    gemm_h<true><<<gg, 256>>>((const __half*)hvc, (const __half*)(hw + 2 * (size_t)nW), b_v, vp, 1.0f, cnt);

    attn_h<<<dim3(TSEQ / 128, BATCH * HEADS), 256>>>(
        (const __half*)qp, (const __half*)kp, (const __half*)vp, cnt, (__half*)ctx);

    gemm_h<false><<<gg, 256>>>((const __half*)ctx, (const __half*)(hw + 3 * (size_t)nW), b_o, out, 1.0f, nullptr);
}